// round 7
// baseline (speedup 1.0000x reference)
#include <cuda_runtime.h>
#include <cstdint>
#include <math.h>

// ============================================================
// CustomMLP: out = gelu(X @ W1 + b1) @ W2 + b2
//   X [8192,1024] fp32   W1 [1024,4096]   W2 [4096,1024]
// Harness ptxas targets plain sm_103 -> tcgen05 unavailable.
// mma.sync.m16n8k8 tf32 path. BM=BN=128, BK=32, 128 threads
// (4 warps, 64x64 warp tiles), cp.async 3-stage, 2 CTAs/SM.
// Operands stored k-PERMUTED (p = (k&3)*8 + k>>2 within each
// 32-block) so fragment loads are single LDS.128.
// GEMM1 epilogue restages the permuted h tile through smem so
// global stores are fully coalesced STG.128.
// All operands tf32-rounded (cvt.rna) for accuracy.
// ============================================================

#define DINLINE __device__ __forceinline__

// ---------------- scratch (no cudaMalloc allowed) ----------------
__device__ alignas(1024) float g_xr [8192ull * 1024];   // X, tf32, k-permuted
__device__ alignas(1024) float g_w1t[4096ull * 1024];   // W1^T [N,K], tf32, k-perm
__device__ alignas(1024) float g_w2t[1024ull * 4096];   // W2^T [N,K], tf32, k-perm
__device__ alignas(1024) float g_h  [8192ull * 4096];   // gelu(.), tf32, k-perm

// ---------------- tile geometry ----------------
constexpr int BM = 128;
constexpr int BN = 128;
constexpr int BK = 32;             // one permuted k-block
constexpr int THREADS = 128;       // 4 warps: 2 (M) x 2 (N), 64x64 warp tile
constexpr int NSTAGES = 3;

constexpr int PAD = 4;             // floats of padding per row
constexpr int LDT = BK + PAD;      // 36 floats row stride
constexpr int LDT4 = LDT / 4;      // 9 float4 per row
constexpr int TILE_B = BM * LDT * 4;          // 18432 bytes per tile
constexpr int STG_B  = 2 * TILE_B;            // 36864 bytes per stage (A+B)
constexpr int SMEM_TOTAL = NSTAGES * STG_B;   // 110592 bytes

// epilogue restage: 128 rows x 132-float stride = 67584 B <= SMEM_TOTAL
constexpr int ERS = 132;

// ---------------- helpers ----------------
DINLINE void cp16(void* s, const void* g) {
    uint32_t a;
    asm("{ .reg .u64 t; cvta.to.shared.u64 t, %1; cvt.u32.u64 %0, t; }"
        : "=r"(a) : "l"(s));
    asm volatile("cp.async.cg.shared.global [%0], [%1], 16;" :: "r"(a), "l"(g));
}
DINLINE void cp_commit() { asm volatile("cp.async.commit_group;" ::: "memory"); }
DINLINE void cp_wait0()  { asm volatile("cp.async.wait_group 0;" ::: "memory"); }
DINLINE void cp_wait1()  { asm volatile("cp.async.wait_group 1;" ::: "memory"); }

DINLINE void mma_tf32(float* d, uint32_t a0, uint32_t a1, uint32_t a2, uint32_t a3,
                      uint32_t b0, uint32_t b1) {
    asm volatile(
        "mma.sync.aligned.m16n8k8.row.col.f32.tf32.tf32.f32 "
        "{%0,%1,%2,%3}, {%4,%5,%6,%7}, {%8,%9}, {%0,%1,%2,%3};"
        : "+f"(d[0]), "+f"(d[1]), "+f"(d[2]), "+f"(d[3])
        : "r"(a0), "r"(a1), "r"(a2), "r"(a3), "r"(b0), "r"(b1));
}

DINLINE float rnd_tf32(float v) {
    uint32_t u;
    asm("cvt.rna.tf32.f32 %0, %1;" : "=r"(u) : "f"(v));
    return __uint_as_float(u);
}
DINLINE uint32_t f2u(float v) { return __float_as_uint(v); }

// ---------------- prep kernels ----------------
// round to tf32 and write k-permuted. K = row length (multiple of 32).
__global__ void cvt_tf32_perm_kernel(const float4* __restrict__ in,
                                     float* __restrict__ out, int K, int n4) {
    int i = blockIdx.x * blockDim.x + threadIdx.x;
    if (i >= n4) return;
    float4 v = in[i];
    int e = i * 4;                  // element index; all 4 in same 32-block
    int m = e / K;
    int k = e - m * K;
    int j = (k >> 2) & 7;
    float* rp = out + (size_t)m * K + (k & ~31);
    rp[j]      = rnd_tf32(v.x);     // (k&3)==0 -> position 0*8+j
    rp[8 + j]  = rnd_tf32(v.y);
    rp[16 + j] = rnd_tf32(v.z);
    rp[24 + j] = rnd_tf32(v.w);
}

// out[C,R] = tf32(in[R,C]^T), out columns (R = K dim) k-permuted. block (32,8)
__global__ void transpose_cvt_perm_kernel(const float* __restrict__ in,
                                          float* __restrict__ out, int R, int C) {
    __shared__ float tile[32][33];
    int c0 = blockIdx.x * 32, r0 = blockIdx.y * 32;
    #pragma unroll
    for (int i = 0; i < 32; i += 8)
        tile[threadIdx.y + i][threadIdx.x] =
            in[(size_t)(r0 + threadIdx.y + i) * C + c0 + threadIdx.x];
    __syncthreads();
    int kp = r0 + (((int)threadIdx.x & 3) << 3) + ((int)threadIdx.x >> 2);
    #pragma unroll
    for (int i = 0; i < 32; i += 8)
        out[(size_t)(c0 + threadIdx.y + i) * R + kp] =
            rnd_tf32(tile[threadIdx.x][threadIdx.y + i]);
}

// ---------------- tile loads (gmem -> smem, cp.async) ----------------
// 128 threads: tid&7 = 16B chunk, tid>>3 = base row; 8 rows each for A and B.
template<int KG>
DINLINE void load_tiles(const float* __restrict__ A, const float* __restrict__ Bt,
                        int m0, int n0, int kb, char* stage) {
    const int tid = threadIdx.x;
    const int c = tid & 7;
    const int r0 = tid >> 3;
    const int kcol = kb * BK + c * 4;
    float* sA = reinterpret_cast<float*>(stage);
    float* sB = reinterpret_cast<float*>(stage + TILE_B);
    #pragma unroll
    for (int t = 0; t < 8; t++) {
        int row = r0 + t * 16;
        cp16(sA + row * LDT + c * 4, A  + (size_t)(m0 + row) * KG + kcol);
        cp16(sB + row * LDT + c * 4, Bt + (size_t)(n0 + row) * KG + kcol);
    }
}

template<bool G>
DINLINE float epi_op(float acc, float b) {
    float t = acc + b;
    if (G) {
        t = 0.5f * t * (1.0f + erff(t * 0.70710678118654752f));
        t = rnd_tf32(t);   // h feeds the tf32 GEMM2
    }
    return t;
}

// ---------------- GEMM: C[BMxBN] = A[m0:,:] @ Bt[n0:,:]^T (+bias, opt gelu) ----------------
template<int KG, int NG, bool DO_GELU>
__global__ void __launch_bounds__(THREADS, 2)
mlp_gemm_kernel(const float* __restrict__ A, const float* __restrict__ Bt,
                const float* __restrict__ bias, float* __restrict__ C) {
    extern __shared__ char smem[];
    const int tid  = threadIdx.x;
    const int lane = tid & 31;
    const int warp = tid >> 5;
    const int wm = warp & 1;          // 2 warps along M
    const int wn = warp >> 1;         // 2 warps along N
    const int g  = lane >> 2;         // groupID (0..7)
    const int tk = lane & 3;          // threadID_in_group (0..3)
    const int m0 = blockIdx.y * BM, n0 = blockIdx.x * BN;
    const int KT = KG / BK;

    float acc[4][8][4];               // [mt][nt][frag]
    #pragma unroll
    for (int i = 0; i < 4; i++)
        #pragma unroll
        for (int j = 0; j < 8; j++)
            #pragma unroll
            for (int q = 0; q < 4; q++) acc[i][j][q] = 0.0f;

    // prologue: prefetch stages 0, 1
    load_tiles<KG>(A, Bt, m0, n0, 0, smem);
    cp_commit();
    load_tiles<KG>(A, Bt, m0, n0, 1, smem + STG_B);
    cp_commit();

    for (int kb = 0; kb < KT; kb++) {
        if (kb + 1 < KT) cp_wait1(); else cp_wait0();   // stage kb resident
        __syncthreads();
        if (kb + 2 < KT) {
            load_tiles<KG>(A, Bt, m0, n0, kb + 2, smem + ((kb + 2) % NSTAGES) * STG_B);
            cp_commit();
        }
        const char* stage = smem + (kb % NSTAGES) * STG_B;
        const float4* sA4 = reinterpret_cast<const float4*>(stage);
        const float4* sB4 = reinterpret_cast<const float4*>(stage + TILE_B);

        // permuted layout: float4 at r*9 + 2*tk + p holds, for phase p,
        // k-steps ks=2p,2p+1: (.x,.y)=(a0,a2)|(b0,b1)@ks=2p; (.z,.w)@ks=2p+1.
        // B fragments (shared by all mt) hoisted; A loaded per-mt to cap
        // register liveness (~180 live vs 255 budget -> no spills).
        #pragma unroll
        for (int p = 0; p < 2; p++) {
            float4 bqv[8];
            #pragma unroll
            for (int nt = 0; nt < 8; nt++) {
                int n = wn * 64 + nt * 8 + g;
                bqv[nt] = sB4[n * LDT4 + 2 * tk + p];
            }
            #pragma unroll
            for (int mt = 0; mt < 4; mt++) {
                int r = wm * 64 + mt * 16 + g;
                float4 aLo = sA4[r * LDT4 + 2 * tk + p];
                float4 aHi = sA4[(r + 8) * LDT4 + 2 * tk + p];
                #pragma unroll
                for (int s = 0; s < 2; s++) {
                    uint32_t a0 = f2u(s ? aLo.z : aLo.x);
                    uint32_t a1 = f2u(s ? aHi.z : aHi.x);
                    uint32_t a2 = f2u(s ? aLo.w : aLo.y);
                    uint32_t a3 = f2u(s ? aHi.w : aHi.y);
                    #pragma unroll
                    for (int nt = 0; nt < 8; nt++) {
                        uint32_t b0 = f2u(s ? bqv[nt].z : bqv[nt].x);
                        uint32_t b1 = f2u(s ? bqv[nt].w : bqv[nt].y);
                        mma_tf32(acc[mt][nt], a0, a1, a2, a3, b0, b1);
                    }
                }
            }
        }
        __syncthreads();   // stage kb fully consumed before it is refilled
    }
    // (trailing __syncthreads of last iteration fences smem for epilogue reuse)

    // ---------------- epilogue ----------------
    if (DO_GELU) {
        // GEMM1: gelu + bias, restage the k-PERMUTED tile through smem so
        // global stores are dense STG.128 (100% sector efficiency).
        float* es = reinterpret_cast<float*>(smem);
        #pragma unroll
        for (int mt = 0; mt < 4; mt++) {
            const int lr = wm * 64 + mt * 16 + g;
            #pragma unroll
            for (int nt = 0; nt < 8; nt++) {
                const int lc = wn * 64 + nt * 8 + 2 * tk;
                const int blk = lc & ~31;
                const int k0 = lc & 31;
                const int p0 = ((k0 & 3) << 3) | (k0 >> 2);
                const int p1 = (((k0 + 1) & 3) << 3) | ((k0 + 1) >> 2);
                const float2 bv = *reinterpret_cast<const float2*>(bias + n0 + lc);
                es[lr * ERS + blk + p0]       = epi_op<true>(acc[mt][nt][0], bv.x);
                es[lr * ERS + blk + p1]       = epi_op<true>(acc[mt][nt][1], bv.y);
                es[(lr + 8) * ERS + blk + p0] = epi_op<true>(acc[mt][nt][2], bv.x);
                es[(lr + 8) * ERS + blk + p1] = epi_op<true>(acc[mt][nt][3], bv.y);
            }
        }
        __syncthreads();
        #pragma unroll
        for (int t = 0; t < 32; t++) {
            int idx = t * 128 + tid;          // 0..4095
            int row = idx >> 5;               // 0..127
            int c4  = idx & 31;               // float4 column
            float4 v = *reinterpret_cast<const float4*>(es + row * ERS + c4 * 4);
            *reinterpret_cast<float4*>(C + (size_t)(m0 + row) * NG + n0 + c4 * 4) = v;
        }
    } else {
        // GEMM2: bias only, direct float2 stores (already sector-efficient).
        #pragma unroll
        for (int mt = 0; mt < 4; mt++) {
            const int r = m0 + wm * 64 + mt * 16 + g;
            #pragma unroll
            for (int nt = 0; nt < 8; nt++) {
                const int cN = n0 + wn * 64 + nt * 8 + 2 * tk;
                const float2 bv = *reinterpret_cast<const float2*>(bias + cN);
                float2 v0, v1;
                v0.x = epi_op<false>(acc[mt][nt][0], bv.x);
                v0.y = epi_op<false>(acc[mt][nt][1], bv.y);
                v1.x = epi_op<false>(acc[mt][nt][2], bv.x);
                v1.y = epi_op<false>(acc[mt][nt][3], bv.y);
                *reinterpret_cast<float2*>(C + (size_t)(r)     * NG + cN) = v0;
                *reinterpret_cast<float2*>(C + (size_t)(r + 8) * NG + cN) = v1;
            }
        }
    }
}

// ---------------- launch ----------------
extern "C" void kernel_launch(void* const* d_in, const int* in_sizes, int n_in,
                              void* d_out, int out_size) {
    const float* x  = (const float*)d_in[0];   // [4,2048,1024] -> [8192,1024]
    const float* w1 = (const float*)d_in[1];   // [1024,4096]
    const float* b1 = (const float*)d_in[2];   // [4096]
    const float* w2 = (const float*)d_in[3];   // [4096,1024]
    const float* b2 = (const float*)d_in[4];   // [1024]
    float* out = (float*)d_out;                // [8192,1024]

    float *xr, *w1t, *w2t, *h;
    cudaGetSymbolAddress((void**)&xr,  g_xr);
    cudaGetSymbolAddress((void**)&w1t, g_w1t);
    cudaGetSymbolAddress((void**)&w2t, g_w2t);
    cudaGetSymbolAddress((void**)&h,   g_h);

    cudaFuncSetAttribute(mlp_gemm_kernel<1024, 4096, true>,
                         cudaFuncAttributeMaxDynamicSharedMemorySize, SMEM_TOTAL);
    cudaFuncSetAttribute(mlp_gemm_kernel<4096, 1024, false>,
                         cudaFuncAttributeMaxDynamicSharedMemorySize, SMEM_TOTAL);

    // prep: round to tf32 + k-permute X; transpose+round+permute weights to [N,K]
    {
        int n4 = 8192 * 1024 / 4;
        cvt_tf32_perm_kernel<<<(n4 + 255) / 256, 256>>>((const float4*)x, xr, 1024, n4);
        transpose_cvt_perm_kernel<<<dim3(4096 / 32, 1024 / 32), dim3(32, 8)>>>(w1, w1t, 1024, 4096);
        transpose_cvt_perm_kernel<<<dim3(1024 / 32, 4096 / 32), dim3(32, 8)>>>(w2, w2t, 4096, 1024);
    }

    // GEMM1: h = tf32(gelu(X @ W1 + b1))   [8192 x 4096], h stored k-permuted
    mlp_gemm_kernel<1024, 4096, true>
        <<<dim3(4096 / BN, 8192 / BM), THREADS, SMEM_TOTAL>>>(xr, w1t, b1, h);

    // GEMM2: out = h @ W2 + b2             [8192 x 1024]
    mlp_gemm_kernel<4096, 1024, false>
        <<<dim3(1024 / BN, 8192 / BM), THREADS, SMEM_TOTAL>>>(h, w2t, b2, out);
}